// round 1
// baseline (speedup 1.0000x reference)
#include <cuda_runtime.h>
#include <cuda_bf16.h>
#include <math.h>

// Problem dims
#define B_ 64
#define T_ 512
#define D_ 512
#define U_ 1024
#define N4U 4096   // 4*U

// ---------------- scratch (device globals; no runtime allocation) -------------
__device__ float g_xg[(size_t)B_ * T_ * N4U];  // [B, T, 4U] : row (b*T + t)
__device__ float g_h0[B_ * U_];
__device__ float g_h1[B_ * U_];
__device__ float g_c [B_ * U_];

// ---------------- init: zero h0 and c ----------------------------------------
__global__ void lstm_init() {
    int i = blockIdx.x * blockDim.x + threadIdx.x;
    if (i < B_ * U_) { g_h0[i] = 0.f; g_c[i] = 0.f; }
}

// ---------------- input projection GEMM ---------------------------------------
// C[M=32768, N=4096] = A[M, 512] @ W[512, 4096], all fp32 row-major.
// 128x128 tile, BK=16, 256 threads, 8x8 per-thread register tile.
#define PC_BM 128
#define PC_BN 128
#define PC_BK 16

__global__ __launch_bounds__(256, 1)
void lstm_xgemm(const float* __restrict__ A, const float* __restrict__ W) {
    __shared__ float As[PC_BM][PC_BK];       // [m][k]
    __shared__ float Bs[PC_BK][PC_BN + 4];   // [k][n], padded

    const int tid = threadIdx.x;
    const int tx = tid & 15;        // 0..15 -> n
    const int ty = tid >> 4;        // 0..15 -> m
    const int m0 = blockIdx.y * PC_BM;
    const int n0 = blockIdx.x * PC_BN;

    float acc[8][8];
    #pragma unroll
    for (int i = 0; i < 8; i++)
        #pragma unroll
        for (int j = 0; j < 8; j++) acc[i][j] = 0.f;

    for (int k0 = 0; k0 < D_; k0 += PC_BK) {
        // A tile: 128x16 = 512 float4, 2 per thread
        #pragma unroll
        for (int l = 0; l < 2; l++) {
            int i = tid + l * 256;
            int m = i >> 2;
            int kq = (i & 3) << 2;
            float4 v = *(const float4*)(A + (size_t)(m0 + m) * D_ + k0 + kq);
            *(float4*)(&As[m][kq]) = v;
        }
        // B tile: 16x128 = 512 float4, 2 per thread
        #pragma unroll
        for (int l = 0; l < 2; l++) {
            int i = tid + l * 256;
            int kk = i >> 5;
            int nq = (i & 31) << 2;
            float4 v = *(const float4*)(W + (size_t)(k0 + kk) * N4U + n0 + nq);
            *(float4*)(&Bs[kk][nq]) = v;
        }
        __syncthreads();

        #pragma unroll
        for (int kk = 0; kk < PC_BK; kk++) {
            float a[8], b[8];
            #pragma unroll
            for (int i = 0; i < 8; i++) a[i] = As[ty * 8 + i][kk];
            *(float4*)&b[0] = *(float4*)&Bs[kk][tx * 8];
            *(float4*)&b[4] = *(float4*)&Bs[kk][tx * 8 + 4];
            #pragma unroll
            for (int i = 0; i < 8; i++)
                #pragma unroll
                for (int j = 0; j < 8; j++)
                    acc[i][j] = fmaf(a[i], b[j], acc[i][j]);
        }
        __syncthreads();
    }

    #pragma unroll
    for (int i = 0; i < 8; i++) {
        size_t row = (size_t)(m0 + ty * 8 + i) * N4U + n0 + tx * 8;
        *(float4*)(&g_xg[row])     = *(float4*)&acc[i][0];
        *(float4*)(&g_xg[row + 4]) = *(float4*)&acc[i][4];
    }
}

// ---------------- fused recurrent step -----------------------------------------
// One launch per timestep t. 128 blocks; block handles u-tile of 8 units across
// all 4 gates (32 z-columns) for all 64 batch rows, then does the c/h update.
// h double-buffered: reads g_h[t&1], writes g_h[(t+1)&1]. c updated in place
// (each (b,u) owned by exactly one block).
#define ST_BK 32

__global__ __launch_bounds__(256, 2)
void lstm_step(const float* __restrict__ W, int t) {
    const float* __restrict__ h_in = (t & 1) ? g_h1 : g_h0;
    float* __restrict__ h_out      = (t & 1) ? g_h0 : g_h1;

    __shared__ float Hs[ST_BK][66];   // transposed h tile [k][b], padded
    __shared__ float Ws[ST_BK][36];   // [k][cc], padded so float4 rows align
    __shared__ float Zs[32][66];      // z tile [cc][b]

    const int tid = threadIdx.x;
    const int u0 = blockIdx.x * 8;
    const int tr = tid >> 3;  // 0..31 -> row pair
    const int tc = tid & 7;   // 0..7  -> 4 columns

    float acc[2][4];
    #pragma unroll
    for (int i = 0; i < 2; i++)
        #pragma unroll
        for (int j = 0; j < 4; j++) acc[i][j] = 0.f;

    for (int k0 = 0; k0 < U_; k0 += ST_BK) {
        // H tile: 64 x 32 = 512 float4, 2 per thread; store transposed
        #pragma unroll
        for (int l = 0; l < 2; l++) {
            int i = tid + l * 256;
            int b = i >> 3;
            int kq = (i & 7) << 2;
            float4 v = *(const float4*)(h_in + b * U_ + k0 + kq);
            Hs[kq + 0][b] = v.x;
            Hs[kq + 1][b] = v.y;
            Hs[kq + 2][b] = v.z;
            Hs[kq + 3][b] = v.w;
        }
        // W tile: 32 k x 32 cols (4 gates x 8 units), 4 per thread
        #pragma unroll
        for (int l = 0; l < 4; l++) {
            int i = tid + l * 256;
            int kk = i >> 5;
            int cc = i & 31;
            int col = ((cc >> 3) << 10) + u0 + (cc & 7);
            Ws[kk][cc] = W[(size_t)(k0 + kk) * N4U + col];
        }
        __syncthreads();

        #pragma unroll
        for (int kk = 0; kk < ST_BK; kk++) {
            float2 av = *(float2*)&Hs[kk][2 * tr];
            float4 bv = *(float4*)&Ws[kk][4 * tc];
            acc[0][0] = fmaf(av.x, bv.x, acc[0][0]);
            acc[0][1] = fmaf(av.x, bv.y, acc[0][1]);
            acc[0][2] = fmaf(av.x, bv.z, acc[0][2]);
            acc[0][3] = fmaf(av.x, bv.w, acc[0][3]);
            acc[1][0] = fmaf(av.y, bv.x, acc[1][0]);
            acc[1][1] = fmaf(av.y, bv.y, acc[1][1]);
            acc[1][2] = fmaf(av.y, bv.z, acc[1][2]);
            acc[1][3] = fmaf(av.y, bv.w, acc[1][3]);
        }
        __syncthreads();
    }

    // z = h@W + x_gates[t]; stash in smem so gates for the same u meet
    #pragma unroll
    for (int i = 0; i < 2; i++) {
        int b = 2 * tr + i;
        #pragma unroll
        for (int j = 0; j < 4; j++) {
            int cc = 4 * tc + j;
            int col = ((cc >> 3) << 10) + u0 + (cc & 7);
            float z = acc[i][j] + g_xg[((size_t)b * T_ + t) * N4U + col];
            Zs[cc][b] = z;
        }
    }
    __syncthreads();

    // gate + state update: 512 (b,u) cells, 2 per thread
    #pragma unroll
    for (int l = 0; l < 2; l++) {
        int e = tid + l * 256;
        int ul = e & 7;
        int b = e >> 3;
        float zi = Zs[ul][b];
        float zf = Zs[8 + ul][b];
        float zg = Zs[16 + ul][b];
        float zo = Zs[24 + ul][b];
        float iv = 1.f / (1.f + __expf(-zi));
        float fv = 1.f / (1.f + __expf(-zf));
        float gv = tanhf(zg);
        float ov = 1.f / (1.f + __expf(-zo));
        int idx = b * U_ + u0 + ul;
        float cv = fv * g_c[idx] + iv * gv;
        g_c[idx] = cv;
        h_out[idx] = ov * tanhf(cv);
    }
}

// ---------------- final copy: h (in g_h0 after 512 steps) -> d_out -------------
__global__ void lstm_copy_out(float* __restrict__ out) {
    int i = blockIdx.x * blockDim.x + threadIdx.x;
    if (i < B_ * U_) out[i] = g_h0[i];
}

// ---------------- launch --------------------------------------------------------
extern "C" void kernel_launch(void* const* d_in, const int* in_sizes, int n_in,
                              void* d_out, int out_size) {
    const float* x    = (const float*)d_in[0];   // [B, T, D]
    const float* kern = (const float*)d_in[1];   // [D, 4U]
    const float* rec  = (const float*)d_in[2];   // [U, 4U]
    float* out = (float*)d_out;                  // [B, U]

    lstm_init<<<(B_ * U_ + 255) / 256, 256>>>();

    // x viewed as [B*T, D] row-major == A; output row (b*T + t) matches xg layout.
    dim3 pg(N4U / PC_BN, (B_ * T_) / PC_BM);     // (32, 256)
    lstm_xgemm<<<pg, 256>>>(x, kern);

    for (int t = 0; t < T_; t++) {
        lstm_step<<<U_ / 8, 256>>>(rec, t);      // 128 blocks
    }

    lstm_copy_out<<<(B_ * U_ + 255) / 256, 256>>>(out);
}

// round 2
// speedup vs baseline: 1.0734x; 1.0734x over previous
#include <cuda_runtime.h>
#include <cuda_bf16.h>
#include <math.h>

// Problem dims
#define B_ 64
#define T_ 512
#define D_ 512
#define U_ 1024
#define N4U 4096   // 4*U

#define KS 4       // K-splits in the recurrent GEMM
#define KSLEN (U_ / KS)   // 256

// ---------------- scratch (device globals; no runtime allocation) -------------
__device__ float g_xg[(size_t)B_ * T_ * N4U];  // [B, T, 4U] : row (b*T + t)
__device__ float g_h0[B_ * U_];
__device__ float g_h1[B_ * U_];
__device__ float g_c [B_ * U_];
__device__ float g_zp[KS * 128 * B_ * 32];     // [ks][ut][b][cc] partial z
__device__ unsigned g_tk[128];                 // per-u-tile arrival tickets

// ---------------- init: zero h0, c, tickets -----------------------------------
__global__ void lstm_init() {
    int i = blockIdx.x * blockDim.x + threadIdx.x;
    if (i < B_ * U_) { g_h0[i] = 0.f; g_c[i] = 0.f; }
    if (i < 128) g_tk[i] = 0u;
}

// ---------------- input projection GEMM ---------------------------------------
// C[M=32768, N=4096] = A[M, 512] @ W[512, 4096], all fp32 row-major.
// 128x128 tile, BK=16, 256 threads, 8x8 per-thread register tile.
#define PC_BM 128
#define PC_BN 128
#define PC_BK 16

__global__ __launch_bounds__(256, 2)
void lstm_xgemm(const float* __restrict__ A, const float* __restrict__ W) {
    __shared__ float As[PC_BM][PC_BK];       // [m][k]
    __shared__ float Bs[PC_BK][PC_BN + 4];   // [k][n], padded

    const int tid = threadIdx.x;
    const int tx = tid & 15;        // 0..15 -> n
    const int ty = tid >> 4;        // 0..15 -> m
    const int m0 = blockIdx.y * PC_BM;
    const int n0 = blockIdx.x * PC_BN;

    float acc[8][8];
    #pragma unroll
    for (int i = 0; i < 8; i++)
        #pragma unroll
        for (int j = 0; j < 8; j++) acc[i][j] = 0.f;

    for (int k0 = 0; k0 < D_; k0 += PC_BK) {
        #pragma unroll
        for (int l = 0; l < 2; l++) {
            int i = tid + l * 256;
            int m = i >> 2;
            int kq = (i & 3) << 2;
            float4 v = *(const float4*)(A + (size_t)(m0 + m) * D_ + k0 + kq);
            *(float4*)(&As[m][kq]) = v;
        }
        #pragma unroll
        for (int l = 0; l < 2; l++) {
            int i = tid + l * 256;
            int kk = i >> 5;
            int nq = (i & 31) << 2;
            float4 v = *(const float4*)(W + (size_t)(k0 + kk) * N4U + n0 + nq);
            *(float4*)(&Bs[kk][nq]) = v;
        }
        __syncthreads();

        #pragma unroll
        for (int kk = 0; kk < PC_BK; kk++) {
            float a[8], b[8];
            #pragma unroll
            for (int i = 0; i < 8; i++) a[i] = As[ty * 8 + i][kk];
            *(float4*)&b[0] = *(float4*)&Bs[kk][tx * 8];
            *(float4*)&b[4] = *(float4*)&Bs[kk][tx * 8 + 4];
            #pragma unroll
            for (int i = 0; i < 8; i++)
                #pragma unroll
                for (int j = 0; j < 8; j++)
                    acc[i][j] = fmaf(a[i], b[j], acc[i][j]);
        }
        __syncthreads();
    }

    #pragma unroll
    for (int i = 0; i < 8; i++) {
        size_t row = (size_t)(m0 + ty * 8 + i) * N4U + n0 + tx * 8;
        *(float4*)(&g_xg[row])     = *(float4*)&acc[i][0];
        *(float4*)(&g_xg[row + 4]) = *(float4*)&acc[i][4];
    }
}

// ---------------- fused recurrent step (K-split + last-block finisher) ---------
// grid = (KS=4, 128 u-tiles), block = 256 threads.
// Each block: 64x32 tile (all 64 batch rows x 32 z-cols for 8 units' 4 gates)
// over its K-range of 256. Partials go to g_zp. The last-arriving block per
// u-tile (ticket) sums the 4 partials IN FIXED ORDER (deterministic), adds
// x_gates, and does the gate + c/h update.
// h double-buffered: reads g_h[t&1], writes g_h[(t+1)&1].
#define ST_BK 32

__global__ __launch_bounds__(256)
void lstm_step(const float* __restrict__ W, int t) {
    const float* __restrict__ h_in = (t & 1) ? g_h1 : g_h0;
    float* __restrict__ h_out      = (t & 1) ? g_h0 : g_h1;

    __shared__ float Hs[ST_BK][66];   // transposed h tile [k][b]; reused as Zs[cc][b]
    __shared__ float Ws[ST_BK][36];   // [k][cc]
    __shared__ unsigned sflag;

    const int tid = threadIdx.x;
    const int ks = blockIdx.x;        // 0..3
    const int ut = blockIdx.y;        // 0..127
    const int u0 = ut * 8;
    const int tr = tid >> 3;          // 0..31 -> batch row pair
    const int tc = tid & 7;           // 0..7  -> 4 cols

    float acc[2][4];
    #pragma unroll
    for (int i = 0; i < 2; i++)
        #pragma unroll
        for (int j = 0; j < 4; j++) acc[i][j] = 0.f;

    const int kbase = ks * KSLEN;
    for (int k0 = 0; k0 < KSLEN; k0 += ST_BK) {
        // H tile: 64 x 32 = 512 float4, 2 per thread; store transposed
        #pragma unroll
        for (int l = 0; l < 2; l++) {
            int i = tid + l * 256;
            int b = i >> 3;
            int kq = (i & 7) << 2;
            float4 v = *(const float4*)(h_in + b * U_ + kbase + k0 + kq);
            Hs[kq + 0][b] = v.x;
            Hs[kq + 1][b] = v.y;
            Hs[kq + 2][b] = v.z;
            Hs[kq + 3][b] = v.w;
        }
        // W tile: 32 k x 32 cols (4 gates x 8 units), 4 per thread
        #pragma unroll
        for (int l = 0; l < 4; l++) {
            int i = tid + l * 256;
            int kk = i >> 5;
            int cc = i & 31;
            int col = ((cc >> 3) << 10) + u0 + (cc & 7);
            Ws[kk][cc] = W[(size_t)(kbase + k0 + kk) * N4U + col];
        }
        __syncthreads();

        #pragma unroll
        for (int kk = 0; kk < ST_BK; kk++) {
            float2 av = *(float2*)&Hs[kk][2 * tr];
            float4 bv = *(float4*)&Ws[kk][4 * tc];
            acc[0][0] = fmaf(av.x, bv.x, acc[0][0]);
            acc[0][1] = fmaf(av.x, bv.y, acc[0][1]);
            acc[0][2] = fmaf(av.x, bv.z, acc[0][2]);
            acc[0][3] = fmaf(av.x, bv.w, acc[0][3]);
            acc[1][0] = fmaf(av.y, bv.x, acc[1][0]);
            acc[1][1] = fmaf(av.y, bv.y, acc[1][1]);
            acc[1][2] = fmaf(av.y, bv.z, acc[1][2]);
            acc[1][3] = fmaf(av.y, bv.w, acc[1][3]);
        }
        __syncthreads();
    }

    // write this block's partial tile: g_zp[ks][ut][b][cc]
    {
        float* zp = g_zp + ((size_t)(ks * 128 + ut) * B_) * 32;
        #pragma unroll
        for (int i = 0; i < 2; i++) {
            int b = 2 * tr + i;
            *(float4*)(zp + b * 32 + 4 * tc) = *(float4*)&acc[i][0];
        }
    }
    __threadfence();
    __syncthreads();
    if (tid == 0)
        sflag = (atomicAdd(&g_tk[ut], 1u) == (unsigned)(KS - 1)) ? 1u : 0u;
    __syncthreads();
    if (!sflag) return;
    if (tid == 0) g_tk[ut] = 0u;   // reset for next step (kernel-ordered)

    // ---- finisher: z = sum_ks zp (fixed order) + x_gates; stash in Hs as Zs ----
    #pragma unroll
    for (int i = 0; i < 2; i++) {
        int b = 2 * tr + i;
        float4 z4 = make_float4(0.f, 0.f, 0.f, 0.f);
        #pragma unroll
        for (int s = 0; s < KS; s++) {
            float4 p = *(const float4*)(g_zp + ((size_t)(s * 128 + ut) * B_ + b) * 32 + 4 * tc);
            z4.x += p.x; z4.y += p.y; z4.z += p.z; z4.w += p.w;
        }
        #pragma unroll
        for (int j = 0; j < 4; j++) {
            int cc = 4 * tc + j;
            int col = ((cc >> 3) << 10) + u0 + (cc & 7);
            float z = ((j == 0) ? z4.x : (j == 1) ? z4.y : (j == 2) ? z4.z : z4.w)
                    + g_xg[((size_t)b * T_ + t) * N4U + col];
            Hs[cc][b] = z;  // Zs[cc][b]
        }
    }
    __syncthreads();

    // gate + state update: 512 (b,u) cells, 2 per thread
    #pragma unroll
    for (int l = 0; l < 2; l++) {
        int e = tid + l * 256;
        int ul = e & 7;
        int b = e >> 3;
        float zi = Hs[ul][b];
        float zf = Hs[8 + ul][b];
        float zg = Hs[16 + ul][b];
        float zo = Hs[24 + ul][b];
        float iv = 1.f / (1.f + __expf(-zi));
        float fv = 1.f / (1.f + __expf(-zf));
        float gv = tanhf(zg);
        float ov = 1.f / (1.f + __expf(-zo));
        int idx = b * U_ + u0 + ul;
        float cv = fv * g_c[idx] + iv * gv;
        g_c[idx] = cv;
        h_out[idx] = ov * tanhf(cv);
    }
}

// ---------------- final copy: h (in g_h0 after 512 steps) -> d_out -------------
__global__ void lstm_copy_out(float* __restrict__ out) {
    int i = blockIdx.x * blockDim.x + threadIdx.x;
    if (i < B_ * U_) out[i] = g_h0[i];
}

// ---------------- launch --------------------------------------------------------
extern "C" void kernel_launch(void* const* d_in, const int* in_sizes, int n_in,
                              void* d_out, int out_size) {
    const float* x    = (const float*)d_in[0];   // [B, T, D]
    const float* kern = (const float*)d_in[1];   // [D, 4U]
    const float* rec  = (const float*)d_in[2];   // [U, 4U]
    float* out = (float*)d_out;                  // [B, U]

    lstm_init<<<(B_ * U_ + 255) / 256, 256>>>();

    // x viewed as [B*T, D] row-major == A; output row (b*T + t) matches xg layout.
    dim3 pg(N4U / PC_BN, (B_ * T_) / PC_BM);     // (32, 256)
    lstm_xgemm<<<pg, 256>>>(x, kern);

    for (int t = 0; t < T_; t++) {
        dim3 sg(KS, 128);                        // 512 blocks
        lstm_step<<<sg, 256>>>(rec, t);
    }

    lstm_copy_out<<<(B_ * U_ + 255) / 256, 256>>>(out);
}